// round 3
// baseline (speedup 1.0000x reference)
#include <cuda_runtime.h>
#include <cuda_bf16.h>
#include <cstddef>

// score(f) = 1 + tanh(f.W + b)/10 ; e[parent] = score(c0)*e[c0] + score(c1)*e[c1]
// Tree: complete binary, level order, D=21 levels, N = 2^21 - 1 nodes, F = 64.

#define TANH_INV_SCALAR 0.1f

// One warp per parent. Lanes 0-15 handle child0, lanes 16-31 handle child1.
// Each lane loads one float4 of the 64-float feature row (256B, fully coalesced).
__global__ void __launch_bounds__(256)
tree_level_kernel(const float* __restrict__ features,
                  const float* __restrict__ W,
                  const float* __restrict__ bptr,
                  float* __restrict__ energy,
                  int pstart, int nparents)
{
    int gtid = blockIdx.x * blockDim.x + threadIdx.x;
    int warp_id = gtid >> 5;
    if (warp_id >= nparents) return;          // whole warp exits together
    int lane = threadIdx.x & 31;
    int seg  = lane & 15;                      // position within the 16-lane group

    int p = pstart + warp_id;
    int child = 2 * p + 1 + (lane >> 4);       // lanes 0-15: left child; 16-31: right

    const float4* frow = reinterpret_cast<const float4*>(features + (size_t)child * 64);
    float4 v = frow[seg];
    float4 w = reinterpret_cast<const float4*>(W)[seg];
    float dot = v.x * w.x + v.y * w.y + v.z * w.z + v.w * w.w;

    // Reduce across the 16-lane group (xor 8,4,2,1 stays within each half-warp group).
    #pragma unroll
    for (int off = 8; off >= 1; off >>= 1)
        dot += __shfl_xor_sync(0xffffffffu, dot, off);

    float b = __ldg(bptr);
    float contrib = 0.0f;
    if (seg == 0) {
        float s = 1.0f + tanhf(dot + b) * TANH_INV_SCALAR;
        contrib = s * energy[child];
    }
    // Combine sibling contributions: lane 0 <-> lane 16
    float other = __shfl_xor_sync(0xffffffffu, contrib, 16);
    if (lane == 0)
        energy[p] = contrib + other;
}

// Single block handles levels d = dmax .. 1 (parents <= 1024), sync between levels.
// 256 threads keeps register pressure well under the per-SM limit.
__global__ void __launch_bounds__(256)
tree_tail_kernel(const float* __restrict__ features,
                 const float* __restrict__ W,
                 const float* __restrict__ bptr,
                 float* __restrict__ energy,
                 int dmax)
{
    __shared__ float sW[64];
    if (threadIdx.x < 64) sW[threadIdx.x] = W[threadIdx.x];
    __syncthreads();
    float b = __ldg(bptr);

    for (int d = dmax; d >= 1; --d) {
        int np = 1 << (d - 1);
        int pstart = np - 1;
        for (int i = threadIdx.x; i < np; i += blockDim.x) {
            int p = pstart + i;
            float tot = 0.0f;
            for (int c = 0; c < 2; ++c) {
                int ch = 2 * p + 1 + c;
                const float4* f = reinterpret_cast<const float4*>(features + (size_t)ch * 64);
                float dot = 0.0f;
                #pragma unroll
                for (int k = 0; k < 16; ++k) {
                    float4 v = f[k];
                    const float4* wv = reinterpret_cast<const float4*>(sW);
                    float4 w = wv[k];
                    dot += v.x * w.x + v.y * w.y + v.z * w.z + v.w * w.w;
                }
                float s = 1.0f + tanhf(dot + b) * TANH_INV_SCALAR;
                tot += s * energy[ch];
            }
            energy[p] = tot;
        }
        __syncthreads();   // parents of this level become children of the next
    }
}

extern "C" void kernel_launch(void* const* d_in, const int* in_sizes, int n_in,
                              void* d_out, int out_size)
{
    const float* features    = (const float*)d_in[0];   // [N, 64]
    const float* leaf_energy = (const float*)d_in[1];   // [2^20]
    const float* W           = (const float*)d_in[2];   // [64]
    const float* bptr        = (const float*)d_in[3];   // [1]
    float* energy = (float*)d_out;                      // [N]

    const int N_LEAVES = 1 << 20;
    const int leaf_start = N_LEAVES - 1;

    // Seed leaves: energy[leaf_start:] = leaf_energy
    cudaMemcpyAsync(energy + leaf_start, leaf_energy,
                    (size_t)N_LEAVES * sizeof(float), cudaMemcpyDeviceToDevice);

    // Big levels: children at level d = 20 .. 12 (parents 2^19 .. 2^11)
    for (int d = 20; d >= 12; --d) {
        int np = 1 << (d - 1);
        int pstart = np - 1;
        const int threads = 256;
        long long total_threads = (long long)np * 32;
        int blocks = (int)((total_threads + threads - 1) / threads);
        tree_level_kernel<<<blocks, threads>>>(features, W, bptr, energy, pstart, np);
    }

    // Remaining levels d = 11 .. 1 (parents <= 1024) in one block
    tree_tail_kernel<<<1, 256>>>(features, W, bptr, energy, 11);
}

// round 4
// speedup vs baseline: 1.1287x; 1.1287x over previous
#include <cuda_runtime.h>
#include <cuda_bf16.h>
#include <cstddef>

// score(f) = 1 + tanh(f.W + b)/10 ; e[parent] = score(c0)*e[c0] + score(c1)*e[c1]
// Complete binary tree, level order, D=21 levels, N = 2^21 - 1 nodes, F = 64.

#define TANH_INV_SCALAR 0.1f
#define ROWS 128          // children per block
#define PAD  68           // floats per smem row (16 float4 + 1 float4 pad) -> conflict-free

// Each block handles 128 consecutive children of one level:
//  1) stage 128x64 floats to smem via 16 independent coalesced float4 loads/thread
//  2) thread i computes full dot for child i from smem (no shuffles)
//  3) coalesced energy load, contrib to smem, sibling-pair combine, coalesced store
__global__ void __launch_bounds__(ROWS)
level_kernel(const float* __restrict__ features,
             const float* __restrict__ W,
             const float* __restrict__ bptr,
             float* __restrict__ energy,
             int cstart, int pstart)
{
    __shared__ float sF[ROWS * PAD];
    __shared__ float sW[64];
    __shared__ float sB;
    __shared__ float sContrib[ROWS];

    int tid = threadIdx.x;
    if (tid < 64) sW[tid] = W[tid];
    if (tid == 64 % ROWS && tid != 64) {}          // no-op
    if (tid == 0) sB = bptr[0];

    int row0 = blockIdx.x * ROWS;                  // offset within the level
    const float4* g = reinterpret_cast<const float4*>(
        features + (size_t)(cstart + row0) * 64);

    // 2048 float4s per tile; thread t takes t, t+128, ... -> 16 independent loads
    #pragma unroll
    for (int j = 0; j < 16; ++j) {
        int idx = j * ROWS + tid;                  // 0..2047, coalesced in tid
        int r = idx >> 4;                          // row within tile
        int c = idx & 15;                          // float4 column
        float4 v = g[idx];
        *reinterpret_cast<float4*>(&sF[r * PAD + c * 4]) = v;
    }
    __syncthreads();

    // Full dot product for child row `tid` (smem stride 68 -> conflict-free)
    float dot = 0.0f;
    const float4* wv = reinterpret_cast<const float4*>(sW);
    #pragma unroll
    for (int k = 0; k < 16; ++k) {
        float4 v = *reinterpret_cast<const float4*>(&sF[tid * PAD + k * 4]);
        float4 w = wv[k];
        dot += v.x * w.x + v.y * w.y + v.z * w.z + v.w * w.w;
    }
    float s = 1.0f + tanhf(dot + sB) * TANH_INV_SCALAR;

    // Coalesced energy load for this child
    float e = energy[cstart + row0 + tid];
    sContrib[tid] = s * e;
    __syncthreads();

    // Sibling pairs (2i, 2i+1) share parent; threads 0..63 write parents coalesced
    if (tid < ROWS / 2) {
        float pv = sContrib[2 * tid] + sContrib[2 * tid + 1];
        energy[pstart + (row0 >> 1) + tid] = pv;
    }
}

// Single block handles levels d = dmax .. 1 (children <= 2048), sync between levels.
__global__ void __launch_bounds__(256)
tree_tail_kernel(const float* __restrict__ features,
                 const float* __restrict__ W,
                 const float* __restrict__ bptr,
                 float* __restrict__ energy,
                 int dmax)
{
    __shared__ float sW[64];
    if (threadIdx.x < 64) sW[threadIdx.x] = W[threadIdx.x];
    __syncthreads();
    float b = __ldg(bptr);

    for (int d = dmax; d >= 1; --d) {
        int np = 1 << (d - 1);
        int pstart = np - 1;
        for (int i = threadIdx.x; i < np; i += blockDim.x) {
            int p = pstart + i;
            float tot = 0.0f;
            for (int c = 0; c < 2; ++c) {
                int ch = 2 * p + 1 + c;
                const float4* f = reinterpret_cast<const float4*>(features + (size_t)ch * 64);
                float dot = 0.0f;
                #pragma unroll
                for (int k = 0; k < 16; ++k) {
                    float4 v = f[k];
                    float4 w = reinterpret_cast<const float4*>(sW)[k];
                    dot += v.x * w.x + v.y * w.y + v.z * w.z + v.w * w.w;
                }
                float s = 1.0f + tanhf(dot + b) * TANH_INV_SCALAR;
                tot += s * energy[ch];
            }
            energy[p] = tot;
        }
        __syncthreads();
    }
}

extern "C" void kernel_launch(void* const* d_in, const int* in_sizes, int n_in,
                              void* d_out, int out_size)
{
    const float* features    = (const float*)d_in[0];   // [N, 64]
    const float* leaf_energy = (const float*)d_in[1];   // [2^20]
    const float* W           = (const float*)d_in[2];   // [64]
    const float* bptr        = (const float*)d_in[3];   // [1]
    float* energy = (float*)d_out;                      // [N]

    const int N_LEAVES = 1 << 20;
    const int leaf_start = N_LEAVES - 1;

    // Seed leaves: energy[leaf_start:] = leaf_energy
    cudaMemcpyAsync(energy + leaf_start, leaf_energy,
                    (size_t)N_LEAVES * sizeof(float), cudaMemcpyDeviceToDevice);

    // Big levels: children at level d = 20 .. 12
    for (int d = 20; d >= 12; --d) {
        int nchildren = 1 << d;
        int cstart = nchildren - 1;
        int pstart = (1 << (d - 1)) - 1;
        int blocks = nchildren / ROWS;
        level_kernel<<<blocks, ROWS>>>(features, W, bptr, energy, cstart, pstart);
    }

    // Remaining levels d = 11 .. 1 (children <= 2048) in one block
    tree_tail_kernel<<<1, 256>>>(features, W, bptr, energy, 11);
}

// round 5
// speedup vs baseline: 1.4241x; 1.2617x over previous
#include <cuda_runtime.h>
#include <cuda_bf16.h>
#include <cstddef>

// score(f) = 1 + tanh(f.W + b)/10 ; e[parent] = score(c0)*e[c0] + score(c1)*e[c1]
// Complete binary tree, level order, D=21 levels, N = 2^21 - 1, F = 64.
// Single persistent kernel: leaf seed + 20 levels, grid barrier between levels.

#define TANH_INV_SCALAR 0.1f
#define NB      296          // 2 blocks per SM on 148 SMs -> all resident
#define NTHREADS 256
#define NWARPS  (NB * (NTHREADS / 32))

__device__ unsigned g_count = 0;
__device__ volatile unsigned g_gen = 0;

__device__ __forceinline__ void grid_barrier()
{
    __syncthreads();
    if (threadIdx.x == 0) {
        __threadfence();                       // release all prior writes
        unsigned g = g_gen;
        if (atomicAdd(&g_count, 1u) == NB - 1u) {
            g_count = 0;
            __threadfence();
            g_gen = g + 1u;                    // release the others
        } else {
            while (g_gen == g) { __nanosleep(32); }
            __threadfence();                   // acquire
        }
    }
    __syncthreads();
}

__global__ void __launch_bounds__(NTHREADS, 2)
tree_all_kernel(const float* __restrict__ features,
                const float* __restrict__ leaf_energy,
                const float* __restrict__ W,
                const float* __restrict__ bptr,
                float* __restrict__ energy)
{
    const int tid   = threadIdx.x;
    const int lane  = tid & 31;
    const int gtid  = blockIdx.x * NTHREADS + tid;
    const int gwarp = gtid >> 5;

    // Per-lane W slice: column (lane & 15) of the 16 float4 chunks of W.
    const float4 wv = reinterpret_cast<const float4*>(W)[lane & 15];
    const float  b  = __ldg(bptr);

    // ---- Seed leaves: energy[2^20-1 ..] = leaf_energy ----
    {
        const int NLEAF = 1 << 20;
        const int leaf_start = NLEAF - 1;
        for (int i = gtid; i < NLEAF; i += NB * NTHREADS)
            __stcg(&energy[leaf_start + i], __ldg(&leaf_energy[i]));
    }
    grid_barrier();

    // ---- Levels d = 20 .. 4 : warp-tiles of 16 children ----
    for (int d = 20; d >= 4; --d) {
        const int nc     = 1 << d;
        const int cstart = nc - 1;
        const int pstart = (nc >> 1) - 1;
        const int ntiles = nc >> 4;

        for (int tile = gwarp; tile < ntiles; tile += NWARPS) {
            const int cbase = cstart + tile * 16;
            const float4* g = reinterpret_cast<const float4*>(
                features + (size_t)cbase * 64);

            // 8 independent coalesced float4 loads; col = lane&15 for all j.
            float part[8];
            #pragma unroll
            for (int j = 0; j < 8; ++j) {
                float4 v = __ldg(&g[j * 32 + lane]);
                part[j] = v.x * wv.x + v.y * wv.y + v.z * wv.z + v.w * wv.w;
            }
            // Reduce each j across the 16-lane half-groups.
            #pragma unroll
            for (int j = 0; j < 8; ++j) {
                #pragma unroll
                for (int off = 8; off >= 1; off >>= 1)
                    part[j] += __shfl_xor_sync(0xffffffffu, part[j], off);
            }
            // Lane layout: h = lane>>4 selects sibling (0/1), jj = lane&15 picks pair.
            const int h  = lane >> 4;
            const int jj = lane & 15;
            float dv = part[0];
            dv = (jj == 1) ? part[1] : dv;
            dv = (jj == 2) ? part[2] : dv;
            dv = (jj == 3) ? part[3] : dv;
            dv = (jj == 4) ? part[4] : dv;
            dv = (jj == 5) ? part[5] : dv;
            dv = (jj == 6) ? part[6] : dv;
            dv = (jj == 7) ? part[7] : dv;

            float contrib = 0.0f;
            if (jj < 8) {
                float s = 1.0f + tanhf(dv + b) * TANH_INV_SCALAR;
                float e = __ldcg(&energy[cbase + 2 * jj + h]);
                contrib = s * e;
            }
            float other = __shfl_xor_sync(0xffffffffu, contrib, 16);
            if (h == 0 && jj < 8)
                __stcg(&energy[pstart + tile * 8 + jj], contrib + other);
        }
        grid_barrier();
    }

    // ---- Levels d = 3 .. 1 (nc = 8, 4, 2): single warp, lane per child ----
    for (int d = 3; d >= 1; --d) {
        const int nc     = 1 << d;
        const int cstart = nc - 1;
        const int pstart = (nc >> 1) - 1;
        if (blockIdx.x == 0 && tid < 32) {
            float contrib = 0.0f;
            if (lane < nc) {
                const int ch = cstart + lane;
                const float* f = features + (size_t)ch * 64;
                float dot = 0.0f;
                #pragma unroll
                for (int k = 0; k < 64; ++k)
                    dot += __ldg(&f[k]) * __ldg(&W[k]);
                float s = 1.0f + tanhf(dot + b) * TANH_INV_SCALAR;
                contrib = s * __ldcg(&energy[ch]);
            }
            float other = __shfl_xor_sync(0xffffffffu, contrib, 1);
            if (lane < nc && (lane & 1) == 0)
                __stcg(&energy[pstart + (lane >> 1)], contrib + other);
        }
        grid_barrier();
    }
}

extern "C" void kernel_launch(void* const* d_in, const int* in_sizes, int n_in,
                              void* d_out, int out_size)
{
    const float* features    = (const float*)d_in[0];   // [N, 64]
    const float* leaf_energy = (const float*)d_in[1];   // [2^20]
    const float* W           = (const float*)d_in[2];   // [64]
    const float* bptr        = (const float*)d_in[3];   // [1]
    float* energy = (float*)d_out;                      // [N]

    tree_all_kernel<<<NB, NTHREADS>>>(features, leaf_energy, W, bptr, energy);
}